// round 3
// baseline (speedup 1.0000x reference)
#include <cuda_runtime.h>
#include <cuda_bf16.h>

// Problem constants (MultiHeadAttention: B=2, S=2048, E=1024, H=16, DH=64, no softmax)
#define B_   2
#define S_   2048
#define E_   1024
#define H_   16
#define DH_  64
#define MTOT (B_ * S_)          // 4096 rows
#define EPS_ 1e-9f
#define SCALE_ 0.125f           // 1/sqrt(DH)

// Scratch (no cudaMalloc allowed): 4 x 16 MB fp32 buffers
__device__ float g_Q[B_ * S_ * E_];
__device__ float g_K[B_ * S_ * E_];
__device__ float g_V[B_ * S_ * E_];
__device__ float g_A[B_ * S_ * E_];

// ---- packed fp32x2 helpers (sm_103a FFMA2 — ptxas never auto-generates) ----
__device__ __forceinline__ unsigned long long pack2(float lo, float hi) {
    unsigned long long r;
    asm("mov.b64 %0, {%1, %2};" : "=l"(r) : "f"(lo), "f"(hi));
    return r;
}
__device__ __forceinline__ void unpack2(unsigned long long v, float& lo, float& hi) {
    asm("mov.b64 {%0, %1}, %2;" : "=f"(lo), "=f"(hi) : "l"(v));
}
__device__ __forceinline__ void ffma2(unsigned long long& d,
                                      unsigned long long a, unsigned long long b) {
    asm("fma.rn.f32x2 %0, %1, %2, %0;" : "+l"(d) : "l"(a), "l"(b));
}

// ---------------------------------------------------------------------------
// C[M,N] = A[M,K] @ W[N,K]^T + bias[N]
// 128x128 block tile, BK=16, 256 threads, 8x8 per-thread microtile.
// Double-buffered smem + register-staged gmem prefetch. Inner product via
// packed fma.rn.f32x2 (acc paired along n; per-thread n cols consecutive).
// ---------------------------------------------------------------------------
__global__ void __launch_bounds__(256) gemm_bias_kernel(
    const float* __restrict__ A, const float* __restrict__ W,
    const float* __restrict__ bias, float* __restrict__ C,
    int M, int N, int K)
{
    __shared__ float As[2][16][132];
    __shared__ float Bs[2][16][132];

    const int tid = threadIdx.x;
    const int tx  = tid & 15;        // n microtile: cols tx*8 .. tx*8+7
    const int ty  = tid >> 4;        // m microtile: rows ty*8 .. ty*8+7
    const int m0  = blockIdx.y * 128;
    const int n0  = blockIdx.x * 128;

    const int ldrow0 = (tid + 0)   >> 2;          // 0..63
    const int ldrow1 = (tid + 256) >> 2;          // 64..127
    const int ldkc   = (tid & 3) << 2;            // 0,4,8,12

    const float* Aptr0 = A + (size_t)(m0 + ldrow0) * K + ldkc;
    const float* Aptr1 = A + (size_t)(m0 + ldrow1) * K + ldkc;
    const float* Wptr0 = W + (size_t)(n0 + ldrow0) * K + ldkc;
    const float* Wptr1 = W + (size_t)(n0 + ldrow1) * K + ldkc;

    float4 pa0, pa1, pb0, pb1;

    unsigned long long acc2[8][4];   // [m-row][n-pair]
#pragma unroll
    for (int i = 0; i < 8; ++i)
#pragma unroll
        for (int j = 0; j < 4; ++j) acc2[i][j] = 0ull;  // {+0.f, +0.f}

    // Prologue: fill buffer 0
    pa0 = *(const float4*)(Aptr0);
    pa1 = *(const float4*)(Aptr1);
    pb0 = *(const float4*)(Wptr0);
    pb1 = *(const float4*)(Wptr1);
    As[0][ldkc + 0][ldrow0] = pa0.x; As[0][ldkc + 1][ldrow0] = pa0.y;
    As[0][ldkc + 2][ldrow0] = pa0.z; As[0][ldkc + 3][ldrow0] = pa0.w;
    As[0][ldkc + 0][ldrow1] = pa1.x; As[0][ldkc + 1][ldrow1] = pa1.y;
    As[0][ldkc + 2][ldrow1] = pa1.z; As[0][ldkc + 3][ldrow1] = pa1.w;
    Bs[0][ldkc + 0][ldrow0] = pb0.x; Bs[0][ldkc + 1][ldrow0] = pb0.y;
    Bs[0][ldkc + 2][ldrow0] = pb0.z; Bs[0][ldkc + 3][ldrow0] = pb0.w;
    Bs[0][ldkc + 0][ldrow1] = pb1.x; Bs[0][ldkc + 1][ldrow1] = pb1.y;
    Bs[0][ldkc + 2][ldrow1] = pb1.z; Bs[0][ldkc + 3][ldrow1] = pb1.w;
    __syncthreads();

    int p = 0;
    for (int k0 = 0; k0 < K; k0 += 16) {
        const bool has_next = (k0 + 16) < K;
        if (has_next) {
            pa0 = *(const float4*)(Aptr0 + k0 + 16);
            pa1 = *(const float4*)(Aptr1 + k0 + 16);
            pb0 = *(const float4*)(Wptr0 + k0 + 16);
            pb1 = *(const float4*)(Wptr1 + k0 + 16);
        }

#pragma unroll
        for (int kk = 0; kk < 16; ++kk) {
            float ar[8];
            *(float4*)&ar[0] = *(const float4*)&As[p][kk][ty * 8];
            *(float4*)&ar[4] = *(const float4*)&As[p][kk][ty * 8 + 4];
            unsigned long long br2[4];
            {   // two LDS.128 worth of B pairs
                const ulonglong2* bp = (const ulonglong2*)&Bs[p][kk][tx * 8];
                ulonglong2 b01 = bp[0], b23 = bp[1];
                br2[0] = b01.x; br2[1] = b01.y; br2[2] = b23.x; br2[3] = b23.y;
            }
#pragma unroll
            for (int i = 0; i < 8; ++i) {
                unsigned long long a2 = pack2(ar[i], ar[i]);
#pragma unroll
                for (int j = 0; j < 4; ++j) ffma2(acc2[i][j], a2, br2[j]);
            }
        }

        if (has_next) {
            const int q = p ^ 1;
            As[q][ldkc + 0][ldrow0] = pa0.x; As[q][ldkc + 1][ldrow0] = pa0.y;
            As[q][ldkc + 2][ldrow0] = pa0.z; As[q][ldkc + 3][ldrow0] = pa0.w;
            As[q][ldkc + 0][ldrow1] = pa1.x; As[q][ldkc + 1][ldrow1] = pa1.y;
            As[q][ldkc + 2][ldrow1] = pa1.z; As[q][ldkc + 3][ldrow1] = pa1.w;
            Bs[q][ldkc + 0][ldrow0] = pb0.x; Bs[q][ldkc + 1][ldrow0] = pb0.y;
            Bs[q][ldkc + 2][ldrow0] = pb0.z; Bs[q][ldkc + 3][ldrow0] = pb0.w;
            Bs[q][ldkc + 0][ldrow1] = pb1.x; Bs[q][ldkc + 1][ldrow1] = pb1.y;
            Bs[q][ldkc + 2][ldrow1] = pb1.z; Bs[q][ldkc + 3][ldrow1] = pb1.w;
            __syncthreads();
            p = q;
        }
    }

    // Epilogue: unpack, add bias, store
#pragma unroll
    for (int i = 0; i < 8; ++i) {
        int m = m0 + ty * 8 + i;
#pragma unroll
        for (int j = 0; j < 4; ++j) {
            int n = n0 + tx * 8 + 2 * j;
            float lo, hi; unpack2(acc2[i][j], lo, hi);
            float2 o; o.x = lo + bias[n]; o.y = hi + bias[n + 1];
            *(float2*)(C + (size_t)m * N + n) = o;
        }
    }
}

// ---------------------------------------------------------------------------
// Fused linear attention (NO softmax):
//   O[b,h,q,:] = sum_k s(q,k) * V[b,h,k,:],  s = mask ? (q.k)/8 : 1e-9
// One block per (q-tile 64, h, b). 256 threads (tx 0..15, ty 0..15).
// Thread owns q rows ty*4+i; paired k (and d) = 2*tx + 32*j  (j=0,1) so all
// K/V/score accesses are 64-bit and conflict-free; inner products use FFMA2.
// Smem: Qst[d][q] (loaded once), KSs = K^T [d][k] then scores [q][k],
// Vs natural [k][d]. 48 KB static.
// ---------------------------------------------------------------------------
__global__ void __launch_bounds__(256) attn_kernel(
    const float* __restrict__ Q, const float* __restrict__ Kp,
    const float* __restrict__ Vp, const int* __restrict__ mask,
    float* __restrict__ O)
{
    __shared__ float Qst[64 * 64];   // [d][q]
    __shared__ float KSs[64 * 64];   // phase A: K^T [d][k]; phase B: scores [q][k]
    __shared__ float Vs [64 * 64];   // [k][d]

    const int b  = blockIdx.z;
    const int h  = blockIdx.y;
    const int q0 = blockIdx.x * 64;
    const int tid = threadIdx.x;
    const int tx  = tid & 15;
    const int ty  = tid >> 4;

    // Load Q tile, transposed into Qst[d][q]
    {
        const float* Qb = Q + ((size_t)(b * S_ + q0)) * E_ + h * DH_;
#pragma unroll
        for (int it = 0; it < 4; ++it) {
            int idx = tid + it * 256;    // 0..1023
            int row = idx >> 4;          // q row 0..63
            int dc  = (idx & 15) << 2;   // d chunk
            float4 v = *(const float4*)(Qb + (size_t)row * E_ + dc);
            Qst[(dc + 0) * 64 + row] = v.x;
            Qst[(dc + 1) * 64 + row] = v.y;
            Qst[(dc + 2) * 64 + row] = v.z;
            Qst[(dc + 3) * 64 + row] = v.w;
        }
    }

    unsigned long long oacc2[4][2];   // [q-row i][d-pair j2], d = 2*tx + 32*j2
#pragma unroll
    for (int i = 0; i < 4; ++i) { oacc2[i][0] = 0ull; oacc2[i][1] = 0ull; }

    const int* mbase = mask + (size_t)b * S_ * S_ + (size_t)q0 * S_;

    for (int kt = 0; kt < S_; kt += 64) {
        __syncthreads();   // previous tile's consumers done before overwriting smem

        // Load K (transposed -> KSs[d][k]) and V (natural -> Vs[k][d])
        const float* Kb = Kp + ((size_t)(b * S_ + kt)) * E_ + h * DH_;
        const float* Vb = Vp + ((size_t)(b * S_ + kt)) * E_ + h * DH_;
#pragma unroll
        for (int it = 0; it < 4; ++it) {
            int idx = tid + it * 256;
            int row = idx >> 4;
            int dc  = (idx & 15) << 2;
            float4 kv = *(const float4*)(Kb + (size_t)row * E_ + dc);
            KSs[(dc + 0) * 64 + row] = kv.x;
            KSs[(dc + 1) * 64 + row] = kv.y;
            KSs[(dc + 2) * 64 + row] = kv.z;
            KSs[(dc + 3) * 64 + row] = kv.w;
            float4 vv = *(const float4*)(Vb + (size_t)row * E_ + dc);
            *(float4*)&Vs[row * 64 + dc] = vv;
        }
        __syncthreads();

        // S = Q @ K^T: packed pairs, k = 2*tx + 32*j
        unsigned long long s2[4][2];
#pragma unroll
        for (int i = 0; i < 4; ++i) { s2[i][0] = 0ull; s2[i][1] = 0ull; }

#pragma unroll 8
        for (int d = 0; d < 64; ++d) {
            float qr[4];
            *(float4*)&qr[0] = *(const float4*)&Qst[d * 64 + ty * 4];
            unsigned long long kr0 = *(const unsigned long long*)&KSs[d * 64 + 2 * tx];
            unsigned long long kr1 = *(const unsigned long long*)&KSs[d * 64 + 2 * tx + 32];
#pragma unroll
            for (int i = 0; i < 4; ++i) {
                unsigned long long a2 = pack2(qr[i], qr[i]);
                ffma2(s2[i][0], a2, kr0);
                ffma2(s2[i][1], a2, kr1);
            }
        }

        // Mask + scale (masked -> EPS; no softmax). Mask pair loads (int2).
        float2 sv[4][2];
#pragma unroll
        for (int i = 0; i < 4; ++i)
#pragma unroll
            for (int j = 0; j < 2; ++j) {
                int2 mv = *(const int2*)(mbase + (size_t)(ty * 4 + i) * S_ + kt + 2 * tx + 32 * j);
                float lo, hi; unpack2(s2[i][j], lo, hi);
                sv[i][j].x = mv.x ? lo * SCALE_ : EPS_;
                sv[i][j].y = mv.y ? hi * SCALE_ : EPS_;
            }

        __syncthreads();   // all K reads complete before overwriting KSs with scores
#pragma unroll
        for (int i = 0; i < 4; ++i)
#pragma unroll
            for (int j = 0; j < 2; ++j)
                *(float2*)&KSs[(ty * 4 + i) * 64 + 2 * tx + 32 * j] = sv[i][j];
        __syncthreads();

        // O += S @ V  (d pairs; ss rows loaded 4-wide)
#pragma unroll 4
        for (int k0 = 0; k0 < 64; k0 += 4) {
            float4 ss[4];
#pragma unroll
            for (int i = 0; i < 4; ++i)
                ss[i] = *(const float4*)&KSs[(ty * 4 + i) * 64 + k0];
#pragma unroll
            for (int kk = 0; kk < 4; ++kk) {
                int k = k0 + kk;
                unsigned long long vv0 = *(const unsigned long long*)&Vs[k * 64 + 2 * tx];
                unsigned long long vv1 = *(const unsigned long long*)&Vs[k * 64 + 2 * tx + 32];
#pragma unroll
                for (int i = 0; i < 4; ++i) {
                    float s = (kk == 0) ? ss[i].x : (kk == 1) ? ss[i].y
                             : (kk == 2) ? ss[i].z : ss[i].w;
                    unsigned long long sb = pack2(s, s);
                    ffma2(oacc2[i][0], sb, vv0);
                    ffma2(oacc2[i][1], sb, vv1);
                }
            }
        }
    }

    // Store O tile back to [B,S,E] layout (heads interleaved in E)
    float* Ob = O + ((size_t)(b * S_ + q0)) * E_ + h * DH_;
#pragma unroll
    for (int i = 0; i < 4; ++i)
#pragma unroll
        for (int j2 = 0; j2 < 2; ++j2) {
            float lo, hi; unpack2(oacc2[i][j2], lo, hi);
            float2 o; o.x = lo; o.y = hi;
            *(float2*)(Ob + (size_t)(ty * 4 + i) * E_ + 2 * tx + 32 * j2) = o;
        }
}

// ---------------------------------------------------------------------------
extern "C" void kernel_launch(void* const* d_in, const int* in_sizes, int n_in,
                              void* d_out, int out_size)
{
    const float* query = (const float*)d_in[0];
    const float* key   = (const float*)d_in[1];
    const float* value = (const float*)d_in[2];
    const int*   mask  = (const int*)  d_in[3];
    const float* Wq    = (const float*)d_in[4];
    const float* bq    = (const float*)d_in[5];
    const float* Wk    = (const float*)d_in[6];
    const float* bk    = (const float*)d_in[7];
    const float* Wv    = (const float*)d_in[8];
    const float* bv    = (const float*)d_in[9];
    const float* Wo    = (const float*)d_in[10];
    const float* bo    = (const float*)d_in[11];
    float* out = (float*)d_out;

    float *gq, *gk, *gv, *ga;
    cudaGetSymbolAddress((void**)&gq, g_Q);
    cudaGetSymbolAddress((void**)&gk, g_K);
    cudaGetSymbolAddress((void**)&gv, g_V);
    cudaGetSymbolAddress((void**)&ga, g_A);

    dim3 gblk(256);
    dim3 ggrid(E_ / 128, MTOT / 128);   // (8, 32)

    gemm_bias_kernel<<<ggrid, gblk>>>(query, Wq, bq, gq, MTOT, E_, E_);
    gemm_bias_kernel<<<ggrid, gblk>>>(key,   Wk, bk, gk, MTOT, E_, E_);
    gemm_bias_kernel<<<ggrid, gblk>>>(value, Wv, bv, gv, MTOT, E_, E_);

    dim3 agrid(S_ / 64, H_, B_);        // (32, 16, 2)
    attn_kernel<<<agrid, dim3(256)>>>(gq, gk, gv, mask, ga);

    gemm_bias_kernel<<<ggrid, gblk>>>(ga, Wo, bo, out, MTOT, E_, E_);
}

// round 16
// speedup vs baseline: 2.1135x; 2.1135x over previous
#include <cuda_runtime.h>
#include <cuda_bf16.h>
#include <cstdint>

// Problem constants (MultiHeadAttention: B=2, S=2048, E=1024, H=16, DH=64, no softmax)
#define B_   2
#define S_   2048
#define E_   1024
#define H_   16
#define DH_  64
#define MTOT (B_ * S_)          // 4096 rows
#define EPS_ 1e-9f
#define SCALE_ 0.125f           // 1/sqrt(DH)

// fp32 scratch
__device__ float g_Q[B_ * S_ * E_];
__device__ float g_K[B_ * S_ * E_];
__device__ float g_V[B_ * S_ * E_];
__device__ float g_A[B_ * S_ * E_];
// bf16 split scratch (reused across sequential projections)
__device__ __nv_bfloat16 g_in_hi[MTOT * E_];
__device__ __nv_bfloat16 g_in_lo[MTOT * E_];
__device__ __nv_bfloat16 g_w_hi[E_ * E_];
__device__ __nv_bfloat16 g_w_lo[E_ * E_];

// =========================== warp-mma helpers (baseline PTX) ================
__device__ __forceinline__ void mma_bf16(float* c, const uint32_t* a, const uint32_t* b) {
    asm volatile(
        "mma.sync.aligned.m16n8k16.row.col.f32.bf16.bf16.f32 "
        "{%0,%1,%2,%3}, {%4,%5,%6,%7}, {%8,%9}, {%0,%1,%2,%3};"
        : "+f"(c[0]), "+f"(c[1]), "+f"(c[2]), "+f"(c[3])
        : "r"(a[0]), "r"(a[1]), "r"(a[2]), "r"(a[3]), "r"(b[0]), "r"(b[1]));
}
__device__ __forceinline__ void ldm4(uint32_t* r, uint32_t addr) {
    asm volatile("ldmatrix.sync.aligned.m8n8.x4.shared.b16 {%0,%1,%2,%3}, [%4];"
                 : "=r"(r[0]), "=r"(r[1]), "=r"(r[2]), "=r"(r[3]) : "r"(addr));
}
__device__ __forceinline__ void ldm2(uint32_t* r, uint32_t addr) {
    asm volatile("ldmatrix.sync.aligned.m8n8.x2.shared.b16 {%0,%1}, [%2];"
                 : "=r"(r[0]), "=r"(r[1]) : "r"(addr));
}

// ============================================================================
// Split fp32 -> bf16 hi/lo  (x = hi + lo)
// ============================================================================
__global__ void __launch_bounds__(256) split_kernel(
    const float* __restrict__ x, __nv_bfloat16* __restrict__ hi,
    __nv_bfloat16* __restrict__ lo, int n4)
{
    int i = blockIdx.x * 256 + threadIdx.x;
    if (i >= n4) return;
    float4 v = *(const float4*)(x + (size_t)i * 4);
    __nv_bfloat16 h[4], l[4];
    float vv[4] = {v.x, v.y, v.z, v.w};
#pragma unroll
    for (int j = 0; j < 4; ++j) {
        h[j] = __float2bfloat16(vv[j]);
        l[j] = __float2bfloat16(vv[j] - __bfloat162float(h[j]));
    }
    *(uint2*)(hi + (size_t)i * 4) = *(const uint2*)h;
    *(uint2*)(lo + (size_t)i * 4) = *(const uint2*)l;
}

// ============================================================================
// Tensor-core projection GEMM (HMMA via mma.sync, 3-term bf16 split):
//   C[M=4096,N=1024] = Ah@Wh^T + Ah@Wl^T + Al@Wh^T + bias   (fp32 accum)
// Block 128x128, 8 warps in 2x4 (m x n), warp tile 64x32 (4x4 m16n8k16 frags).
// K-chunk 32 bf16 per smem stage; rows padded to 80B so all ldmatrix row-
// address sets land in 32 distinct banks.
// ============================================================================
#define GK_   1024
#define GN_   1024
#define ROWB  80          // padded row bytes (32 bf16 data + 16 bf16 pad)
#define TILEB (128 * ROWB)

__global__ void __launch_bounds__(256) mma_gemm_kernel(
    const __nv_bfloat16* __restrict__ Ah, const __nv_bfloat16* __restrict__ Al,
    const __nv_bfloat16* __restrict__ Bh, const __nv_bfloat16* __restrict__ Bl,
    const float* __restrict__ bias, float* __restrict__ C)
{
    __shared__ char sm[4 * TILEB];   // Ah | Al | Bh | Bl  (40 KB)
    char* sAh = sm;
    char* sAl = sm + TILEB;
    char* sBh = sm + 2 * TILEB;
    char* sBl = sm + 3 * TILEB;

    const int tid  = threadIdx.x;
    const int lane = tid & 31;
    const int w    = tid >> 5;
    const int wm   = w >> 2;          // 0..1 (m)
    const int wn   = w & 3;           // 0..3 (n)
    const int m0   = blockIdx.y * 128;
    const int n0   = blockIdx.x * 128;

    const uint32_t uAh = (uint32_t)__cvta_generic_to_shared(sAh);
    const uint32_t uAl = (uint32_t)__cvta_generic_to_shared(sAl);
    const uint32_t uBh = (uint32_t)__cvta_generic_to_shared(sBh);
    const uint32_t uBl = (uint32_t)__cvta_generic_to_shared(sBl);

    float acc[4][4][4];               // [mi][ni][c0..c3]
#pragma unroll
    for (int mi = 0; mi < 4; ++mi)
#pragma unroll
        for (int ni = 0; ni < 4; ++ni)
#pragma unroll
            for (int r = 0; r < 4; ++r) acc[mi][ni][r] = 0.0f;

    // ldmatrix lane-derived address components
    const int amat = lane >> 3;       // 0..3
    const int arow = lane & 7;
    const int aoff = (amat & 1) * 8 + arow;   // row offset within 16-row frag
    const int akb  = (amat >> 1) * 16;        // 0 or 16 bytes (k 0-7 / 8-15)
    const int blane = lane & 15;
    const int brow = blane & 7;
    const int bkb  = (blane >> 3) * 16;

    for (int kc = 0; kc < GK_; kc += 32) {
        __syncthreads();   // previous chunk's frag reads complete

        // Load 4 tiles: 128 rows x 32 bf16 (64B) each -> 512 16B-granules; 2/thread
#pragma unroll
        for (int t = 0; t < 2; ++t) {
            int idx = tid + t * 256;           // 0..511
            int row = idx >> 2;                // 0..127
            int g   = idx & 3;                 // 16B granule in row
            size_t ga = (size_t)(m0 + row) * GK_ + kc + g * 8;
            size_t gb = (size_t)(n0 + row) * GK_ + kc + g * 8;
            int so = row * ROWB + g * 16;
            *(uint4*)(sAh + so) = *(const uint4*)(Ah + ga);
            *(uint4*)(sAl + so) = *(const uint4*)(Al + ga);
            *(uint4*)(sBh + so) = *(const uint4*)(Bh + gb);
            *(uint4*)(sBl + so) = *(const uint4*)(Bl + gb);
        }
        __syncthreads();

#pragma unroll
        for (int s = 0; s < 2; ++s) {          // two k16 steps per chunk
            uint32_t ah[4][4], al[4][4], bh[4][2], bl[4][2];
#pragma unroll
            for (int mi = 0; mi < 4; ++mi) {
                int row = wm * 64 + mi * 16 + aoff;
                uint32_t off = (uint32_t)(row * ROWB + s * 32 + akb);
                ldm4(ah[mi], uAh + off);
                ldm4(al[mi], uAl + off);
            }
#pragma unroll
            for (int ni = 0; ni < 4; ++ni) {
                int nrow = wn * 32 + ni * 8 + brow;
                uint32_t off = (uint32_t)(nrow * ROWB + s * 32 + bkb);
                ldm2(bh[ni], uBh + off);
                ldm2(bl[ni], uBl + off);
            }
#pragma unroll
            for (int mi = 0; mi < 4; ++mi)
#pragma unroll
                for (int ni = 0; ni < 4; ++ni) {
                    mma_bf16(acc[mi][ni], ah[mi], bh[ni]);
                    mma_bf16(acc[mi][ni], ah[mi], bl[ni]);
                    mma_bf16(acc[mi][ni], al[mi], bh[ni]);
                }
        }
    }

    // Epilogue: c0/c1 -> (row, 2c..2c+1), c2/c3 -> (row+8, 2c..2c+1)
    const int erow = lane >> 2;
    const int ecol = (lane & 3) * 2;
#pragma unroll
    for (int mi = 0; mi < 4; ++mi) {
#pragma unroll
        for (int ni = 0; ni < 4; ++ni) {
            int m = m0 + wm * 64 + mi * 16 + erow;
            int n = n0 + wn * 32 + ni * 8 + ecol;
            float2 bv = *(const float2*)(bias + n);
            float2 o0; o0.x = acc[mi][ni][0] + bv.x; o0.y = acc[mi][ni][1] + bv.y;
            float2 o1; o1.x = acc[mi][ni][2] + bv.x; o1.y = acc[mi][ni][3] + bv.y;
            *(float2*)(C + (size_t)m * GN_ + n) = o0;
            *(float2*)(C + (size_t)(m + 8) * GN_ + n) = o1;
        }
    }
}

// ============================================================================
// Fused linear attention (NO softmax) — vectorized contiguous ownership.
//   O[b,h,q,:] = sum_k s(q,k) * V[b,h,k,:],  s = mask ? (q.k)/8 : 1e-9
// Block per (q-tile 64, h, b), 256 threads; thread owns q rows ty*4+i and
// k (resp. d) = 4*tx+j -> all inner-loop smem traffic is LDS.128/STS.128.
// ============================================================================
__global__ void __launch_bounds__(256) attn_kernel(
    const float* __restrict__ Q, const float* __restrict__ Kp,
    const float* __restrict__ Vp, const int* __restrict__ mask,
    float* __restrict__ O)
{
    __shared__ float Qst[64 * 64];   // [d][q]
    __shared__ float KSs[64 * 64];   // phase A: K^T [d][k]; phase B: scores [q][k]
    __shared__ float Vs [64 * 64];   // [k][d]

    const int b  = blockIdx.z;
    const int h  = blockIdx.y;
    const int q0 = blockIdx.x * 64;
    const int tid = threadIdx.x;
    const int tx  = tid & 15;
    const int ty  = tid >> 4;

    {
        const float* Qb = Q + ((size_t)(b * S_ + q0)) * E_ + h * DH_;
#pragma unroll
        for (int it = 0; it < 4; ++it) {
            int idx = tid + it * 256;
            int row = idx >> 4;
            int dc  = (idx & 15) << 2;
            float4 v = *(const float4*)(Qb + (size_t)row * E_ + dc);
            Qst[(dc + 0) * 64 + row] = v.x;
            Qst[(dc + 1) * 64 + row] = v.y;
            Qst[(dc + 2) * 64 + row] = v.z;
            Qst[(dc + 3) * 64 + row] = v.w;
        }
    }

    float oacc[4][4];
#pragma unroll
    for (int i = 0; i < 4; ++i)
#pragma unroll
        for (int j = 0; j < 4; ++j) oacc[i][j] = 0.0f;

    const int* mbase = mask + (size_t)b * S_ * S_ + (size_t)q0 * S_;

    for (int kt = 0; kt < S_; kt += 64) {
        __syncthreads();

        const float* Kb = Kp + ((size_t)(b * S_ + kt)) * E_ + h * DH_;
        const float* Vb = Vp + ((size_t)(b * S_ + kt)) * E_ + h * DH_;
#pragma unroll
        for (int it = 0; it < 4; ++it) {
            int idx = tid + it * 256;
            int row = idx >> 4;
            int dc  = (idx & 15) << 2;
            float4 kv = *(const float4*)(Kb + (size_t)row * E_ + dc);
            KSs[(dc + 0) * 64 + row] = kv.x;
            KSs[(dc + 1) * 64 + row] = kv.y;
            KSs[(dc + 2) * 64 + row] = kv.z;
            KSs[(dc + 3) * 64 + row] = kv.w;
            float4 vv = *(const float4*)(Vb + (size_t)row * E_ + dc);
            *(float4*)&Vs[row * 64 + dc] = vv;
        }
        __syncthreads();

        float s[4][4];
#pragma unroll
        for (int i = 0; i < 4; ++i)
#pragma unroll
            for (int j = 0; j < 4; ++j) s[i][j] = 0.0f;

#pragma unroll 8
        for (int d = 0; d < 64; ++d) {
            float4 qv = *(const float4*)&Qst[d * 64 + ty * 4];
            float4 kv = *(const float4*)&KSs[d * 64 + tx * 4];
            float qr[4] = {qv.x, qv.y, qv.z, qv.w};
            float kr[4] = {kv.x, kv.y, kv.z, kv.w};
#pragma unroll
            for (int i = 0; i < 4; ++i)
#pragma unroll
                for (int j = 0; j < 4; ++j)
                    s[i][j] = fmaf(qr[i], kr[j], s[i][j]);
        }

        float4 sv[4];
#pragma unroll
        for (int i = 0; i < 4; ++i) {
            int4 mv = *(const int4*)(mbase + (size_t)(ty * 4 + i) * S_ + kt + tx * 4);
            sv[i].x = mv.x ? s[i][0] * SCALE_ : EPS_;
            sv[i].y = mv.y ? s[i][1] * SCALE_ : EPS_;
            sv[i].z = mv.z ? s[i][2] * SCALE_ : EPS_;
            sv[i].w = mv.w ? s[i][3] * SCALE_ : EPS_;
        }

        __syncthreads();
#pragma unroll
        for (int i = 0; i < 4; ++i)
            *(float4*)&KSs[(ty * 4 + i) * 64 + tx * 4] = sv[i];
        __syncthreads();

#pragma unroll 4
        for (int k0 = 0; k0 < 64; k0 += 4) {
            float4 ss[4];
#pragma unroll
            for (int i = 0; i < 4; ++i)
                ss[i] = *(const float4*)&KSs[(ty * 4 + i) * 64 + k0];
#pragma unroll
            for (int kk = 0; kk < 4; ++kk) {
                float4 vvv = *(const float4*)&Vs[(k0 + kk) * 64 + tx * 4];
                float vr[4] = {vvv.x, vvv.y, vvv.z, vvv.w};
#pragma unroll
                for (int i = 0; i < 4; ++i) {
                    float scur = (kk == 0) ? ss[i].x : (kk == 1) ? ss[i].y
                               : (kk == 2) ? ss[i].z : ss[i].w;
#pragma unroll
                    for (int j = 0; j < 4; ++j)
                        oacc[i][j] = fmaf(scur, vr[j], oacc[i][j]);
                }
            }
        }
    }

    float* Ob = O + ((size_t)(b * S_ + q0)) * E_ + h * DH_;
#pragma unroll
    for (int i = 0; i < 4; ++i) {
        float4 o;
        o.x = oacc[i][0]; o.y = oacc[i][1]; o.z = oacc[i][2]; o.w = oacc[i][3];
        *(float4*)(Ob + (size_t)(ty * 4 + i) * E_ + tx * 4) = o;
    }
}

// ---------------------------------------------------------------------------
extern "C" void kernel_launch(void* const* d_in, const int* in_sizes, int n_in,
                              void* d_out, int out_size)
{
    const float* query = (const float*)d_in[0];
    const float* key   = (const float*)d_in[1];
    const float* value = (const float*)d_in[2];
    const int*   mask  = (const int*)  d_in[3];
    const float* Wq    = (const float*)d_in[4];
    const float* bq    = (const float*)d_in[5];
    const float* Wk    = (const float*)d_in[6];
    const float* bk    = (const float*)d_in[7];
    const float* Wv    = (const float*)d_in[8];
    const float* bv    = (const float*)d_in[9];
    const float* Wo    = (const float*)d_in[10];
    const float* bo    = (const float*)d_in[11];
    float* out = (float*)d_out;

    float *gq, *gk, *gv, *ga;
    cudaGetSymbolAddress((void**)&gq, g_Q);
    cudaGetSymbolAddress((void**)&gk, g_K);
    cudaGetSymbolAddress((void**)&gv, g_V);
    cudaGetSymbolAddress((void**)&ga, g_A);
    __nv_bfloat16 *ih, *il, *wh, *wl;
    cudaGetSymbolAddress((void**)&ih, g_in_hi);
    cudaGetSymbolAddress((void**)&il, g_in_lo);
    cudaGetSymbolAddress((void**)&wh, g_w_hi);
    cudaGetSymbolAddress((void**)&wl, g_w_lo);

    const int nIn4 = MTOT * E_ / 4;
    const int nW4  = E_ * E_ / 4;
    dim3 cIn((nIn4 + 255) / 256), cW((nW4 + 255) / 256), cB(256);
    dim3 ggrid(GN_ / 128, MTOT / 128);   // (8, 32)

    // Q projection
    split_kernel<<<cIn, cB>>>(query, ih, il, nIn4);
    split_kernel<<<cW,  cB>>>(Wq, wh, wl, nW4);
    mma_gemm_kernel<<<ggrid, 256>>>(ih, il, wh, wl, bq, gq);
    // K projection
    split_kernel<<<cIn, cB>>>(key, ih, il, nIn4);
    split_kernel<<<cW,  cB>>>(Wk, wh, wl, nW4);
    mma_gemm_kernel<<<ggrid, 256>>>(ih, il, wh, wl, bk, gk);
    // V projection
    split_kernel<<<cIn, cB>>>(value, ih, il, nIn4);
    split_kernel<<<cW,  cB>>>(Wv, wh, wl, nW4);
    mma_gemm_kernel<<<ggrid, 256>>>(ih, il, wh, wl, bv, gv);

    // Fused masked linear attention (fp32)
    dim3 agrid(S_ / 64, H_, B_);         // (32, 16, 2)
    attn_kernel<<<agrid, dim3(256)>>>(gq, gk, gv, mask, ga);

    // Output projection
    split_kernel<<<cIn, cB>>>(ga, ih, il, nIn4);
    split_kernel<<<cW,  cB>>>(Wo, wh, wl, nW4);
    mma_gemm_kernel<<<ggrid, 256>>>(ih, il, wh, wl, bo, out);
}